// round 8
// baseline (speedup 1.0000x reference)
#include <cuda_runtime.h>
#include <cstdint>

// ---------------- problem constants ----------------
#define BATCH   16
#define N1      4096
#define N2      1024
#define C2      256
#define OUTCH   256
#define KTOT    4096
#define SPLITK  4
#define KPER    (KTOT/SPLITK)   // 1024
#define KT      32              // K tile
#define NT      (KPER/KT)       // 32 tiles
#define BN_EPS  1e-5f

#define CONVW_BLOCKS 64

// smem: 3 stages of (Ws[128*36] + Bs[32*136])
#define WS_STRIDE 36
#define BS_STRIDE 136
#define WS_BUF    (128*WS_STRIDE)        // 4608 floats
#define BS_BUF    (32*BS_STRIDE)         // 4352 floats
#define STG_FLOATS (WS_BUF + BS_BUF)     // 8960 floats = 35840 B
#define SMEM_FLOATS (3*STG_FLOATS)       // 26880 floats = 107520 B

// ---------------- device scratch ----------------
__device__ float  g_Wtf[(size_t)OUTCH * KTOT];                 // 4 MB  tf32-rounded W
__device__ float  g_interp[(size_t)BATCH * N1 * C2];           // 67 MB tf32-rounded A[b][n][c]
__device__ float  g_yp[SPLITK][(size_t)BATCH * OUTCH * C2];    // 16 MB partials
__device__ float  g_y [(size_t)BATCH * OUTCH * C2];
__device__ float  g_sum[C2];
__device__ float  g_sumsq[C2];

// ---------------- helpers ----------------
__device__ __forceinline__ uint32_t smem_u32(const void* p) {
    uint32_t a;
    asm("{ .reg .u64 t; cvta.to.shared.u64 t, %1; cvt.u32.u64 %0, t; }" : "=r"(a) : "l"(p));
    return a;
}
__device__ __forceinline__ float tf32r(float x) {
    uint32_t u;
    asm("cvt.rna.tf32.f32 %0, %1;" : "=r"(u) : "f"(x));
    return __uint_as_float(u);
}
__device__ __forceinline__ void cp16(uint32_t dst, const void* src) {
    asm volatile("cp.async.cg.shared.global [%0], [%1], 16;" :: "r"(dst), "l"(src) : "memory");
}
#define CP_COMMIT()  asm volatile("cp.async.commit_group;" ::: "memory")
#define CP_WAIT(n)   asm volatile("cp.async.wait_group %0;" :: "n"(n) : "memory")

__device__ __forceinline__ void mma_tf32(float* d, const uint32_t* a, const uint32_t* b) {
    asm volatile(
        "mma.sync.aligned.m16n8k8.row.col.f32.tf32.tf32.f32 "
        "{%0,%1,%2,%3}, {%4,%5,%6,%7}, {%8,%9}, {%0,%1,%2,%3};"
        : "+f"(d[0]), "+f"(d[1]), "+f"(d[2]), "+f"(d[3])
        : "r"(a[0]), "r"(a[1]), "r"(a[2]), "r"(a[3]), "r"(b[0]), "r"(b[1]));
}

// ---------------- kernel 1: fused convW + zero-stats + topk + interp ----------------
// blocks [0, 64): convert W1 -> g_Wtf (each thread 16 float4, strided)
// blocks [64, 320): per (b, chunk-of-256-points): 3-NN scan + coalesced interp
__global__ __launch_bounds__(256)
void fused_pre_kernel(const float* __restrict__ W1,
                      const float* __restrict__ x2,
                      const float* __restrict__ xyz1,
                      const float* __restrict__ xyz2) {
    int t = threadIdx.x;

    if (blockIdx.x < CONVW_BLOCKS) {
        if (blockIdx.x == 0) {
            g_sum[t] = 0.f;
            g_sumsq[t] = 0.f;
        }
        // OUTCH*KTOT/4 = 262144 float4 over 64 blocks x 256 threads -> 16 each
        const float4* src = (const float4*)W1;
        float4*       dst = (float4*)g_Wtf;
        int base = blockIdx.x * 256 + t;
#pragma unroll
        for (int i = 0; i < 16; ++i) {
            int idx = base + i * (CONVW_BLOCKS * 256);
            float4 v = src[idx];
            dst[idx] = make_float4(tf32r(v.x), tf32r(v.y), tf32r(v.z), tf32r(v.w));
        }
        return;
    }

    // ---- topk + interp part ----
    __shared__ float4 sq[N2];          // (qx,qy,qz,|q|^2)  16 KB
    __shared__ int    sIdx[256 * 3];
    __shared__ float  sWgt[256 * 3];

    int blk = blockIdx.x - CONVW_BLOCKS;
    int b = blk >> 4;
    int nchunk = blk & 15;

    const float* p2 = xyz2 + (size_t)b * N2 * 3;
    for (int j = t; j < N2; j += 256) {
        float qx = p2[j * 3 + 0], qy = p2[j * 3 + 1], qz = p2[j * 3 + 2];
        sq[j] = make_float4(qx, qy, qz, fmaf(qx, qx, fmaf(qy, qy, qz * qz)));
    }
    __syncthreads();

    int n = nchunk * 256 + t;
    const float* p1 = xyz1 + ((size_t)b * N1 + n) * 3;
    float px = p1[0], py = p1[1], pz = p1[2];
    float px2 = -2.f * px, py2 = -2.f * py, pz2 = -2.f * pz;
    float pp = fmaf(px, px, fmaf(py, py, pz * pz));

    float d0 = 3.4e38f, d1 = 3.4e38f, d2 = 3.4e38f;
    int   i0 = 0, i1 = 0, i2 = 0;
#pragma unroll 8
    for (int j = 0; j < N2; ++j) {
        float4 q = sq[j];
        float d = fmaf(px2, q.x, fmaf(py2, q.y, fmaf(pz2, q.z, q.w)));
        if (d < d2) {
            if (d < d1) {
                d2 = d1; i2 = i1;
                if (d < d0) { d1 = d0; i1 = i0; d0 = d; i0 = j; }
                else        { d1 = d;  i1 = j; }
            } else { d2 = d; i2 = j; }
        }
    }
    float r0 = 1.f / (d0 + pp + 1e-8f);
    float r1 = 1.f / (d1 + pp + 1e-8f);
    float r2 = 1.f / (d2 + pp + 1e-8f);
    float inv = 1.f / (r0 + r1 + r2);
    sIdx[t * 3 + 0] = i0; sIdx[t * 3 + 1] = i1; sIdx[t * 3 + 2] = i2;
    sWgt[t * 3 + 0] = r0 * inv; sWgt[t * 3 + 1] = r1 * inv; sWgt[t * 3 + 2] = r2 * inv;
    __syncthreads();

    // coalesced interpolation of this block's 256 points
    int lane = t & 63;          // channel quad
    int psub = t >> 6;          // 0..3
    int c = lane * 4;
    const float* xb = x2 + (size_t)b * N2 * C2 + c;
    size_t outbase = ((size_t)b * N1 + nchunk * 256) * C2 + c;
#pragma unroll 4
    for (int i = 0; i < 64; ++i) {
        int pl = i * 4 + psub;  // local point (warp-uniform -> broadcast LDS)
        int j0 = sIdx[pl * 3 + 0], j1 = sIdx[pl * 3 + 1], j2 = sIdx[pl * 3 + 2];
        float w0 = sWgt[pl * 3 + 0], w1 = sWgt[pl * 3 + 1], w2 = sWgt[pl * 3 + 2];
        float4 v0 = *(const float4*)(xb + (size_t)j0 * C2);
        float4 v1 = *(const float4*)(xb + (size_t)j1 * C2);
        float4 v2 = *(const float4*)(xb + (size_t)j2 * C2);
        float4 r;
        r.x = tf32r(fmaf(w0, v0.x, fmaf(w1, v1.x, w2 * v2.x)));
        r.y = tf32r(fmaf(w0, v0.y, fmaf(w1, v1.y, w2 * v2.y)));
        r.z = tf32r(fmaf(w0, v0.z, fmaf(w1, v1.z, w2 * v2.z)));
        r.w = tf32r(fmaf(w0, v0.w, fmaf(w1, v1.w, w2 * v2.w)));
        *(float4*)(g_interp + outbase + (size_t)pl * C2) = r;
    }
}

// ---------------- kernel 2: tf32 mma.sync GEMM, 3-stage cp.async pipeline ----------------
// grid = b(16) x Mtile(2) x Ntile(2) x splitK(4) = 256 CTAs, 256 threads
__global__ __launch_bounds__(256, 2)
void gemm_mma_kernel() {
    extern __shared__ float sm[];
    const uint32_t smb = smem_u32(sm);

    int bid = blockIdx.x;
    int s   = bid & 3;
    int mtb = (bid >> 2) & 1;
    int ntb = (bid >> 3) & 1;
    int b   = bid >> 4;
    int o0 = mtb * 128, c0 = ntb * 128, k0 = s * KPER;

    int t = threadIdx.x;
    int w = t >> 5, lane = t & 31;
    int g = lane >> 2, kq = lane & 3;
    int warp_m = (w & 3) * 32;
    int warp_n = (w >> 2) * 64;

    const float* Wg = g_Wtf + (size_t)o0 * KTOT + k0;
    const float* Bg = g_interp + ((size_t)b * N1 + k0) * C2 + c0;

    int wm[4], wq4[4], bk[4], bq4[4];
    uint32_t wdst[4], bdst[4];
#pragma unroll
    for (int i = 0; i < 4; ++i) {
        int li = i * 256 + t;
        wm[i]  = li >> 3;        wq4[i] = (li & 7) * 4;
        bk[i]  = li >> 5;        bq4[i] = (li & 31) * 4;
        wdst[i] = (uint32_t)((wm[i] * WS_STRIDE + wq4[i]) * 4);
        bdst[i] = (uint32_t)((WS_BUF + bk[i] * BS_STRIDE + bq4[i]) * 4);
    }

    float acc[2][8][4];
#pragma unroll
    for (int mt = 0; mt < 2; ++mt)
#pragma unroll
        for (int nt = 0; nt < 8; ++nt)
#pragma unroll
            for (int r = 0; r < 4; ++r) acc[mt][nt][r] = 0.f;

#pragma unroll
    for (int pre = 0; pre < 2; ++pre) {
        uint32_t sb = smb + (uint32_t)(pre * STG_FLOATS * 4);
        int kg = pre * KT;
#pragma unroll
        for (int i = 0; i < 4; ++i) {
            cp16(sb + wdst[i], Wg + (size_t)wm[i] * KTOT + kg + wq4[i]);
            cp16(sb + bdst[i], Bg + (size_t)(kg + bk[i]) * C2 + bq4[i]);
        }
        CP_COMMIT();
    }

    int cur = 0;
    int nxt2 = 2 * STG_FLOATS;
    for (int kt = 0; kt < NT; ++kt) {
        if (kt == NT - 1) { CP_WAIT(0); } else { CP_WAIT(1); }
        __syncthreads();

        if (kt + 2 < NT) {
            uint32_t sb = smb + (uint32_t)(nxt2 * 4);
            int kg = (kt + 2) * KT;
#pragma unroll
            for (int i = 0; i < 4; ++i) {
                cp16(sb + wdst[i], Wg + (size_t)wm[i] * KTOT + kg + wq4[i]);
                cp16(sb + bdst[i], Bg + (size_t)(kg + bk[i]) * C2 + bq4[i]);
            }
            CP_COMMIT();
        }

        const float* Ws = sm + cur;
        const float* Bs = sm + cur + WS_BUF;
#pragma unroll
        for (int ks = 0; ks < 4; ++ks) {
            int kb = ks * 8;
            uint32_t a[2][4], bb[8][2];
#pragma unroll
            for (int mt = 0; mt < 2; ++mt) {
                const float* ab = Ws + (warp_m + mt * 16 + g) * WS_STRIDE + kb + kq;
                a[mt][0] = __float_as_uint(ab[0]);
                a[mt][1] = __float_as_uint(ab[8 * WS_STRIDE]);
                a[mt][2] = __float_as_uint(ab[4]);
                a[mt][3] = __float_as_uint(ab[8 * WS_STRIDE + 4]);
            }
#pragma unroll
            for (int nt = 0; nt < 8; ++nt) {
                const float* bbp = Bs + (kb + kq) * BS_STRIDE + warp_n + nt * 8 + g;
                bb[nt][0] = __float_as_uint(bbp[0]);
                bb[nt][1] = __float_as_uint(bbp[4 * BS_STRIDE]);
            }
#pragma unroll
            for (int mt = 0; mt < 2; ++mt)
#pragma unroll
                for (int nt = 0; nt < 8; ++nt)
                    mma_tf32(acc[mt][nt], a[mt], bb[nt]);
        }

        cur  += STG_FLOATS; if (cur  == 3 * STG_FLOATS) cur  = 0;
        nxt2 += STG_FLOATS; if (nxt2 == 3 * STG_FLOATS) nxt2 = 0;
    }

    float* out = g_yp[s] + ((size_t)b * OUTCH + o0) * C2 + c0;
#pragma unroll
    for (int mt = 0; mt < 2; ++mt) {
        int r0 = warp_m + mt * 16 + g;
#pragma unroll
        for (int nt = 0; nt < 8; ++nt) {
            int col = warp_n + nt * 8 + kq * 2;
            *(float2*)(out + (size_t)r0 * C2 + col)       = make_float2(acc[mt][nt][0], acc[mt][nt][1]);
            *(float2*)(out + (size_t)(r0 + 8) * C2 + col) = make_float2(acc[mt][nt][2], acc[mt][nt][3]);
        }
    }
}

// ---------------- kernel 3: reduce partials + bias + BN stats ----------------
__global__ void reduce_kernel(const float* __restrict__ b1) {
    int c = threadIdx.x;
    int row0 = blockIdx.x * 16;
    float s1 = 0.f, s2 = 0.f;
    for (int r = 0; r < 16; ++r) {
        int row = row0 + r;
        int o = row & (OUTCH - 1);
        size_t idx = (size_t)row * C2 + c;
        float v = b1[o];
#pragma unroll
        for (int s = 0; s < SPLITK; ++s) v += g_yp[s][idx];
        g_y[idx] = v;
        s1 += v;
        s2 = fmaf(v, v, s2);
    }
    atomicAdd(&g_sum[c], s1);
    atomicAdd(&g_sumsq[c], s2);
}

// ---------------- kernel 4: BN + ReLU ----------------
__global__ void bn_kernel(const float* __restrict__ gamma,
                          const float* __restrict__ beta,
                          float* __restrict__ out) {
    int c = threadIdx.x;
    int row = blockIdx.x;
    const float invN = 1.f / (BATCH * OUTCH);
    float mean = g_sum[c] * invN;
    float var  = fmaf(g_sumsq[c], invN, -mean * mean);
    float rstd = rsqrtf(var + BN_EPS);
    float v = g_y[(size_t)row * C2 + c];
    float r = fmaf(gamma[c] * rstd, v - mean, beta[c]);
    out[(size_t)row * C2 + c] = fmaxf(r, 0.f);
}

// ---------------- launcher ----------------
extern "C" void kernel_launch(void* const* d_in, const int* in_sizes, int n_in,
                              void* d_out, int out_size) {
    const float* x2    = (const float*)d_in[1];
    const float* xyz1  = (const float*)d_in[2];
    const float* xyz2  = (const float*)d_in[3];
    const float* W1    = (const float*)d_in[4];
    const float* b1    = (const float*)d_in[5];
    const float* gamma = (const float*)d_in[6];
    const float* beta  = (const float*)d_in[7];
    float* out = (float*)d_out;

    cudaFuncSetAttribute(gemm_mma_kernel,
                         cudaFuncAttributeMaxDynamicSharedMemorySize,
                         SMEM_FLOATS * 4);

    fused_pre_kernel<<<CONVW_BLOCKS + BATCH * 16, 256>>>(W1, x2, xyz1, xyz2);
    gemm_mma_kernel<<<BATCH * 2 * 2 * SPLITK, 256, SMEM_FLOATS * 4>>>();
    reduce_kernel<<<(BATCH * OUTCH) / 16, C2>>>(b1);
    bn_kernel<<<BATCH * OUTCH, C2>>>(gamma, beta, out);
}

// round 9
// speedup vs baseline: 1.0748x; 1.0748x over previous
#include <cuda_runtime.h>
#include <cstdint>

// ---------------- problem constants ----------------
#define BATCH   16
#define N1      4096
#define N2      1024
#define C2      256
#define OUTCH   256
#define KTOT    4096
#define SPLITK  4
#define KPER    (KTOT/SPLITK)   // 1024
#define KT      32              // K tile
#define NT      (KPER/KT)       // 32 tiles
#define BN_EPS  1e-5f

#define CONVW_BLOCKS 64
#define BIAS_BLOCKS  16
#define PRE_BLOCKS   (CONVW_BLOCKS + BIAS_BLOCKS + BATCH * 16)

// smem: 3 stages of (Ws[128*36] + Bs[32*136])
#define WS_STRIDE 36
#define BS_STRIDE 136
#define WS_BUF    (128*WS_STRIDE)        // 4608 floats
#define BS_BUF    (32*BS_STRIDE)         // 4352 floats
#define STG_FLOATS (WS_BUF + BS_BUF)     // 8960 floats
#define SMEM_FLOATS (3*STG_FLOATS)       // 107520 B

// ---------------- device scratch ----------------
__device__ int    g_idx[BATCH * N1 * 3];
__device__ float  g_w  [BATCH * N1 * 3];
__device__ float  g_Wtf[(size_t)OUTCH * KTOT];                 // 4 MB  tf32-rounded W
__device__ float  g_interp[(size_t)BATCH * N1 * C2];           // 67 MB tf32-rounded A[b][n][c]
__device__ float  g_y [(size_t)BATCH * OUTCH * C2];            // 4 MB  bias-init, atomic-accumulated
__device__ float  g_sum[C2];
__device__ float  g_sumsq[C2];

// ---------------- helpers ----------------
__device__ __forceinline__ uint32_t smem_u32(const void* p) {
    uint32_t a;
    asm("{ .reg .u64 t; cvta.to.shared.u64 t, %1; cvt.u32.u64 %0, t; }" : "=r"(a) : "l"(p));
    return a;
}
__device__ __forceinline__ float tf32r(float x) {
    uint32_t u;
    asm("cvt.rna.tf32.f32 %0, %1;" : "=r"(u) : "f"(x));
    return __uint_as_float(u);
}
__device__ __forceinline__ void cp16(uint32_t dst, const void* src) {
    asm volatile("cp.async.cg.shared.global [%0], [%1], 16;" :: "r"(dst), "l"(src) : "memory");
}
#define CP_COMMIT()  asm volatile("cp.async.commit_group;" ::: "memory")
#define CP_WAIT(n)   asm volatile("cp.async.wait_group %0;" :: "n"(n) : "memory")

__device__ __forceinline__ void mma_tf32(float* d, const uint32_t* a, const uint32_t* b) {
    asm volatile(
        "mma.sync.aligned.m16n8k8.row.col.f32.tf32.tf32.f32 "
        "{%0,%1,%2,%3}, {%4,%5,%6,%7}, {%8,%9}, {%0,%1,%2,%3};"
        : "+f"(d[0]), "+f"(d[1]), "+f"(d[2]), "+f"(d[3])
        : "r"(a[0]), "r"(a[1]), "r"(a[2]), "r"(a[3]), "r"(b[0]), "r"(b[1]));
}

// ---------------- kernel 1: pre (convW + zero stats + bias init + topk) ----------------
// blocks [0,64): W -> tf32; block 0 also zeroes BN accumulators
// blocks [64,80): g_y[row][c] = b1[row & 255]
// blocks [80,336): per (b, chunk): 3-NN scan + weights
__global__ __launch_bounds__(256)
void pre_kernel(const float* __restrict__ W1,
                const float* __restrict__ b1,
                const float* __restrict__ xyz1,
                const float* __restrict__ xyz2) {
    int t = threadIdx.x;

    if (blockIdx.x < CONVW_BLOCKS) {
        if (blockIdx.x == 0) {
            g_sum[t] = 0.f;
            g_sumsq[t] = 0.f;
        }
        const float4* src = (const float4*)W1;
        float4*       dst = (float4*)g_Wtf;
        int base = blockIdx.x * 256 + t;
#pragma unroll
        for (int i = 0; i < 16; ++i) {
            int idx = base + i * (CONVW_BLOCKS * 256);
            float4 v = src[idx];
            dst[idx] = make_float4(tf32r(v.x), tf32r(v.y), tf32r(v.z), tf32r(v.w));
        }
        return;
    }
    if (blockIdx.x < CONVW_BLOCKS + BIAS_BLOCKS) {
        int row = (blockIdx.x - CONVW_BLOCKS) * 256 + t;   // 0..4095
        float bias = b1[row & (OUTCH - 1)];
        float4 bv = make_float4(bias, bias, bias, bias);
        float4* dst = (float4*)(g_y + (size_t)row * C2);
#pragma unroll
        for (int i = 0; i < 64; ++i) dst[i] = bv;
        return;
    }

    // ---- topk ----
    __shared__ float4 sq[N2];   // (qx, qy, qz, |q|^2)
    int blk = blockIdx.x - CONVW_BLOCKS - BIAS_BLOCKS;
    int b = blk >> 4;
    int nchunk = blk & 15;

    const float* p2 = xyz2 + (size_t)b * N2 * 3;
    for (int j = t; j < N2; j += 256) {
        float qx = p2[j * 3 + 0], qy = p2[j * 3 + 1], qz = p2[j * 3 + 2];
        sq[j] = make_float4(qx, qy, qz, fmaf(qx, qx, fmaf(qy, qy, qz * qz)));
    }
    __syncthreads();

    int n = nchunk * 256 + t;
    const float* p1 = xyz1 + ((size_t)b * N1 + n) * 3;
    float px = p1[0], py = p1[1], pz = p1[2];
    float px2 = -2.f * px, py2 = -2.f * py, pz2 = -2.f * pz;
    float pp = fmaf(px, px, fmaf(py, py, pz * pz));

    float d0 = 3.4e38f, d1 = 3.4e38f, d2 = 3.4e38f;
    int   i0 = 0, i1 = 0, i2 = 0;
#pragma unroll 8
    for (int j = 0; j < N2; ++j) {
        float4 q = sq[j];
        float d = fmaf(px2, q.x, fmaf(py2, q.y, fmaf(pz2, q.z, q.w)));
        if (d < d2) {
            if (d < d1) {
                d2 = d1; i2 = i1;
                if (d < d0) { d1 = d0; i1 = i0; d0 = d; i0 = j; }
                else        { d1 = d;  i1 = j; }
            } else { d2 = d; i2 = j; }
        }
    }
    float r0 = 1.f / (d0 + pp + 1e-8f);
    float r1 = 1.f / (d1 + pp + 1e-8f);
    float r2 = 1.f / (d2 + pp + 1e-8f);
    float inv = 1.f / (r0 + r1 + r2);
    size_t base = ((size_t)b * N1 + n) * 3;
    g_idx[base + 0] = i0; g_idx[base + 1] = i1; g_idx[base + 2] = i2;
    g_w  [base + 0] = r0 * inv; g_w[base + 1] = r1 * inv; g_w[base + 2] = r2 * inv;
}

// ---------------- kernel 2: interpolation (2 points / thread, tf32-rounded) ----------------
__global__ void interp_kernel(const float* __restrict__ x2) {
    int pair = threadIdx.x >> 6;            // 0..3
    int lane = threadIdx.x & 63;
    int ptA  = blockIdx.x * 8 + pair * 2;
    int ptB  = ptA + 1;
    int b = ptA >> 12;
    int c = lane * 4;

    size_t baseA = (size_t)ptA * 3, baseB = (size_t)ptB * 3;
    int ai0 = g_idx[baseA + 0], ai1 = g_idx[baseA + 1], ai2 = g_idx[baseA + 2];
    int bi0 = g_idx[baseB + 0], bi1 = g_idx[baseB + 1], bi2 = g_idx[baseB + 2];
    float aw0 = g_w[baseA + 0], aw1 = g_w[baseA + 1], aw2 = g_w[baseA + 2];
    float bw0 = g_w[baseB + 0], bw1 = g_w[baseB + 1], bw2 = g_w[baseB + 2];

    const float* xb = x2 + (size_t)b * N2 * C2 + c;
    float4 a0 = *(const float4*)(xb + (size_t)ai0 * C2);
    float4 a1 = *(const float4*)(xb + (size_t)ai1 * C2);
    float4 a2 = *(const float4*)(xb + (size_t)ai2 * C2);
    float4 b0 = *(const float4*)(xb + (size_t)bi0 * C2);
    float4 b1 = *(const float4*)(xb + (size_t)bi1 * C2);
    float4 b2 = *(const float4*)(xb + (size_t)bi2 * C2);

    float4 ra, rb;
    ra.x = tf32r(fmaf(aw0, a0.x, fmaf(aw1, a1.x, aw2 * a2.x)));
    ra.y = tf32r(fmaf(aw0, a0.y, fmaf(aw1, a1.y, aw2 * a2.y)));
    ra.z = tf32r(fmaf(aw0, a0.z, fmaf(aw1, a1.z, aw2 * a2.z)));
    ra.w = tf32r(fmaf(aw0, a0.w, fmaf(aw1, a1.w, aw2 * a2.w)));
    rb.x = tf32r(fmaf(bw0, b0.x, fmaf(bw1, b1.x, bw2 * b2.x)));
    rb.y = tf32r(fmaf(bw0, b0.y, fmaf(bw1, b1.y, bw2 * b2.y)));
    rb.z = tf32r(fmaf(bw0, b0.z, fmaf(bw1, b1.z, bw2 * b2.z)));
    rb.w = tf32r(fmaf(bw0, b0.w, fmaf(bw1, b1.w, bw2 * b2.w)));
    *(float4*)(g_interp + (size_t)ptA * C2 + c) = ra;
    *(float4*)(g_interp + (size_t)ptB * C2 + c) = rb;
}

// ---------------- kernel 3: tf32 mma.sync GEMM, 3-stage pipeline, atomic epilogue ----------------
__global__ __launch_bounds__(256, 2)
void gemm_mma_kernel() {
    extern __shared__ float sm[];
    const uint32_t smb = smem_u32(sm);

    int bid = blockIdx.x;
    int s   = bid & 3;
    int mtb = (bid >> 2) & 1;
    int ntb = (bid >> 3) & 1;
    int b   = bid >> 4;
    int o0 = mtb * 128, c0 = ntb * 128, k0 = s * KPER;

    int t = threadIdx.x;
    int w = t >> 5, lane = t & 31;
    int g = lane >> 2, kq = lane & 3;
    int warp_m = (w & 3) * 32;
    int warp_n = (w >> 2) * 64;

    const float* Wg = g_Wtf + (size_t)o0 * KTOT + k0;
    const float* Bg = g_interp + ((size_t)b * N1 + k0) * C2 + c0;

    int wm[4], wq4[4], bk[4], bq4[4];
    uint32_t wdst[4], bdst[4];
#pragma unroll
    for (int i = 0; i < 4; ++i) {
        int li = i * 256 + t;
        wm[i]  = li >> 3;        wq4[i] = (li & 7) * 4;
        bk[i]  = li >> 5;        bq4[i] = (li & 31) * 4;
        wdst[i] = (uint32_t)((wm[i] * WS_STRIDE + wq4[i]) * 4);
        bdst[i] = (uint32_t)((WS_BUF + bk[i] * BS_STRIDE + bq4[i]) * 4);
    }

    float acc[2][8][4];
#pragma unroll
    for (int mt = 0; mt < 2; ++mt)
#pragma unroll
        for (int nt = 0; nt < 8; ++nt)
#pragma unroll
            for (int r = 0; r < 4; ++r) acc[mt][nt][r] = 0.f;

#pragma unroll
    for (int pre = 0; pre < 2; ++pre) {
        uint32_t sb = smb + (uint32_t)(pre * STG_FLOATS * 4);
        int kg = pre * KT;
#pragma unroll
        for (int i = 0; i < 4; ++i) {
            cp16(sb + wdst[i], Wg + (size_t)wm[i] * KTOT + kg + wq4[i]);
            cp16(sb + bdst[i], Bg + (size_t)(kg + bk[i]) * C2 + bq4[i]);
        }
        CP_COMMIT();
    }

    int cur = 0;
    int nxt2 = 2 * STG_FLOATS;
    for (int kt = 0; kt < NT; ++kt) {
        if (kt == NT - 1) { CP_WAIT(0); } else { CP_WAIT(1); }
        __syncthreads();

        if (kt + 2 < NT) {
            uint32_t sb = smb + (uint32_t)(nxt2 * 4);
            int kg = (kt + 2) * KT;
#pragma unroll
            for (int i = 0; i < 4; ++i) {
                cp16(sb + wdst[i], Wg + (size_t)wm[i] * KTOT + kg + wq4[i]);
                cp16(sb + bdst[i], Bg + (size_t)(kg + bk[i]) * C2 + bq4[i]);
            }
            CP_COMMIT();
        }

        const float* Ws = sm + cur;
        const float* Bs = sm + cur + WS_BUF;
#pragma unroll
        for (int ks = 0; ks < 4; ++ks) {
            int kb = ks * 8;
            uint32_t a[2][4], bb[8][2];
#pragma unroll
            for (int mt = 0; mt < 2; ++mt) {
                const float* ab = Ws + (warp_m + mt * 16 + g) * WS_STRIDE + kb + kq;
                a[mt][0] = __float_as_uint(ab[0]);
                a[mt][1] = __float_as_uint(ab[8 * WS_STRIDE]);
                a[mt][2] = __float_as_uint(ab[4]);
                a[mt][3] = __float_as_uint(ab[8 * WS_STRIDE + 4]);
            }
#pragma unroll
            for (int nt = 0; nt < 8; ++nt) {
                const float* bbp = Bs + (kb + kq) * BS_STRIDE + warp_n + nt * 8 + g;
                bb[nt][0] = __float_as_uint(bbp[0]);
                bb[nt][1] = __float_as_uint(bbp[4 * BS_STRIDE]);
            }
#pragma unroll
            for (int mt = 0; mt < 2; ++mt)
#pragma unroll
                for (int nt = 0; nt < 8; ++nt)
                    mma_tf32(acc[mt][nt], a[mt], bb[nt]);
        }

        cur  += STG_FLOATS; if (cur  == 3 * STG_FLOATS) cur  = 0;
        nxt2 += STG_FLOATS; if (nxt2 == 3 * STG_FLOATS) nxt2 = 0;
    }

    // atomic epilogue into bias-initialized g_y
    float* out = g_y + ((size_t)b * OUTCH + o0) * C2 + c0;
#pragma unroll
    for (int mt = 0; mt < 2; ++mt) {
        int r0 = warp_m + mt * 16 + g;
#pragma unroll
        for (int nt = 0; nt < 8; ++nt) {
            int col = warp_n + nt * 8 + kq * 2;
            float* p0 = out + (size_t)r0 * C2 + col;
            float* p1 = out + (size_t)(r0 + 8) * C2 + col;
            atomicAdd(p0,     acc[mt][nt][0]);
            atomicAdd(p0 + 1, acc[mt][nt][1]);
            atomicAdd(p1,     acc[mt][nt][2]);
            atomicAdd(p1 + 1, acc[mt][nt][3]);
        }
    }
}

// ---------------- kernel 4: BN statistics from final y ----------------
__global__ void stats_kernel() {
    int c = threadIdx.x;
    int row0 = blockIdx.x * 16;
    float s1 = 0.f, s2 = 0.f;
#pragma unroll
    for (int r = 0; r < 16; ++r) {
        float v = g_y[(size_t)(row0 + r) * C2 + c];
        s1 += v;
        s2 = fmaf(v, v, s2);
    }
    atomicAdd(&g_sum[c], s1);
    atomicAdd(&g_sumsq[c], s2);
}

// ---------------- kernel 5: BN + ReLU ----------------
__global__ void bn_kernel(const float* __restrict__ gamma,
                          const float* __restrict__ beta,
                          float* __restrict__ out) {
    int c = threadIdx.x;
    int row = blockIdx.x;
    const float invN = 1.f / (BATCH * OUTCH);
    float mean = g_sum[c] * invN;
    float var  = fmaf(g_sumsq[c], invN, -mean * mean);
    float rstd = rsqrtf(var + BN_EPS);
    float v = g_y[(size_t)row * C2 + c];
    float r = fmaf(gamma[c] * rstd, v - mean, beta[c]);
    out[(size_t)row * C2 + c] = fmaxf(r, 0.f);
}

// ---------------- launcher ----------------
extern "C" void kernel_launch(void* const* d_in, const int* in_sizes, int n_in,
                              void* d_out, int out_size) {
    const float* x2    = (const float*)d_in[1];
    const float* xyz1  = (const float*)d_in[2];
    const float* xyz2  = (const float*)d_in[3];
    const float* W1    = (const float*)d_in[4];
    const float* b1    = (const float*)d_in[5];
    const float* gamma = (const float*)d_in[6];
    const float* beta  = (const float*)d_in[7];
    float* out = (float*)d_out;

    cudaFuncSetAttribute(gemm_mma_kernel,
                         cudaFuncAttributeMaxDynamicSharedMemorySize,
                         SMEM_FLOATS * 4);

    pre_kernel<<<PRE_BLOCKS, 256>>>(W1, b1, xyz1, xyz2);
    interp_kernel<<<(BATCH * N1) / 8, 256>>>(x2);
    gemm_mma_kernel<<<BATCH * 2 * 2 * SPLITK, 256, SMEM_FLOATS * 4>>>();
    stats_kernel<<<(BATCH * OUTCH) / 16, C2>>>();
    bn_kernel<<<BATCH * OUTCH, C2>>>(gamma, beta, out);
}

// round 10
// speedup vs baseline: 1.0999x; 1.0234x over previous
#include <cuda_runtime.h>
#include <cstdint>

// ---------------- problem constants ----------------
#define BATCH   16
#define N1      4096
#define N2      1024
#define C2      256
#define OUTCH   256
#define KTOT    4096
#define SPLITK  4
#define KPER    (KTOT/SPLITK)   // 1024
#define KT      32              // K tile
#define NT      (KPER/KT)       // 32 tiles
#define BN_EPS  1e-5f

// smem: 3 stages of (Ws[128*36] + Bs[32*128 xor-swizzled])
#define WS_STRIDE 36
#define WS_BUF    (128*WS_STRIDE)        // 4608 floats
#define BS_BUF    (32*128)               // 4096 floats (no pad; XOR swizzle)
#define STG_FLOATS (WS_BUF + BS_BUF)     // 8704 floats
#define STG_BYTES  (STG_FLOATS*4)        // 34816 B
#define SMEM_BYTES (3*STG_BYTES)         // 104448 B

// ---------------- device scratch ----------------
__device__ int    g_idx[BATCH * N1 * 3];
__device__ float  g_w  [BATCH * N1 * 3];
__device__ float  g_Wtf[(size_t)OUTCH * KTOT];                 // 4 MB  tf32-rounded W
__device__ float  g_interp[(size_t)BATCH * N1 * C2];           // 67 MB tf32-rounded A[b][n][c]
__device__ float  g_yp[SPLITK][(size_t)BATCH * OUTCH * C2];    // 16 MB partials
__device__ float  g_y [(size_t)BATCH * OUTCH * C2];
__device__ float  g_sum[C2];
__device__ float  g_sumsq[C2];

// ---------------- helpers ----------------
__device__ __forceinline__ uint32_t smem_u32(const void* p) {
    uint32_t a;
    asm("{ .reg .u64 t; cvta.to.shared.u64 t, %1; cvt.u32.u64 %0, t; }" : "=r"(a) : "l"(p));
    return a;
}
__device__ __forceinline__ float tf32r(float x) {
    uint32_t u;
    asm("cvt.rna.tf32.f32 %0, %1;" : "=r"(u) : "f"(x));
    return __uint_as_float(u);
}
__device__ __forceinline__ void cp16(uint32_t dst, const void* src) {
    asm volatile("cp.async.cg.shared.global [%0], [%1], 16;" :: "r"(dst), "l"(src) : "memory");
}
#define CP_COMMIT()  asm volatile("cp.async.commit_group;" ::: "memory")
#define CP_WAIT(n)   asm volatile("cp.async.wait_group %0;" :: "n"(n) : "memory")

__device__ __forceinline__ void ldsm_x4(uint32_t* r, uint32_t addr) {
    asm volatile("ldmatrix.sync.aligned.m8n8.x4.shared.b16 {%0,%1,%2,%3}, [%4];"
                 : "=r"(r[0]), "=r"(r[1]), "=r"(r[2]), "=r"(r[3]) : "r"(addr));
}
__device__ __forceinline__ void lds128(uint32_t* r, uint32_t addr) {
    asm volatile("ld.shared.v4.b32 {%0,%1,%2,%3}, [%4];"
                 : "=r"(r[0]), "=r"(r[1]), "=r"(r[2]), "=r"(r[3]) : "r"(addr));
}
__device__ __forceinline__ void mma_tf32(float* d, const uint32_t* a, uint32_t b0, uint32_t b1) {
    asm volatile(
        "mma.sync.aligned.m16n8k8.row.col.f32.tf32.tf32.f32 "
        "{%0,%1,%2,%3}, {%4,%5,%6,%7}, {%8,%9}, {%0,%1,%2,%3};"
        : "+f"(d[0]), "+f"(d[1]), "+f"(d[2]), "+f"(d[3])
        : "r"(a[0]), "r"(a[1]), "r"(a[2]), "r"(a[3]), "r"(b0), "r"(b1));
}

// ---------------- kernel 0: W -> tf32 copy + BN accumulator zeroing ----------------
__global__ void convW_kernel(const float* __restrict__ W1) {
    if (blockIdx.x == 0) {
        g_sum[threadIdx.x] = 0.f;
        g_sumsq[threadIdx.x] = 0.f;
    }
    int i = blockIdx.x * 256 + threadIdx.x;   // float4 index
    float4 v = ((const float4*)W1)[i];
    ((float4*)g_Wtf)[i] = make_float4(tf32r(v.x), tf32r(v.y), tf32r(v.z), tf32r(v.w));
}

// ---------------- kernel 1: 3-NN + weights (dot-product form, packed smem) ----------------
__global__ void topk_kernel(const float* __restrict__ xyz1,
                            const float* __restrict__ xyz2) {
    __shared__ float4 sq[N2];   // (qx, qy, qz, |q|^2)
    int b = blockIdx.x >> 4;
    int nchunk = blockIdx.x & 15;

    const float* p2 = xyz2 + (size_t)b * N2 * 3;
    for (int j = threadIdx.x; j < N2; j += 256) {
        float qx = p2[j * 3 + 0], qy = p2[j * 3 + 1], qz = p2[j * 3 + 2];
        sq[j] = make_float4(qx, qy, qz, fmaf(qx, qx, fmaf(qy, qy, qz * qz)));
    }
    __syncthreads();

    int n = nchunk * 256 + threadIdx.x;
    const float* p1 = xyz1 + ((size_t)b * N1 + n) * 3;
    float px = p1[0], py = p1[1], pz = p1[2];
    float px2 = -2.f * px, py2 = -2.f * py, pz2 = -2.f * pz;
    float pp = fmaf(px, px, fmaf(py, py, pz * pz));

    float d0 = 3.4e38f, d1 = 3.4e38f, d2 = 3.4e38f;
    int   i0 = 0, i1 = 0, i2 = 0;
#pragma unroll 8
    for (int j = 0; j < N2; ++j) {
        float4 q = sq[j];
        float d = fmaf(px2, q.x, fmaf(py2, q.y, fmaf(pz2, q.z, q.w)));
        if (d < d2) {
            if (d < d1) {
                d2 = d1; i2 = i1;
                if (d < d0) { d1 = d0; i1 = i0; d0 = d; i0 = j; }
                else        { d1 = d;  i1 = j; }
            } else { d2 = d; i2 = j; }
        }
    }
    float r0 = 1.f / (d0 + pp + 1e-8f);
    float r1 = 1.f / (d1 + pp + 1e-8f);
    float r2 = 1.f / (d2 + pp + 1e-8f);
    float inv = 1.f / (r0 + r1 + r2);
    size_t base = ((size_t)b * N1 + n) * 3;
    g_idx[base + 0] = i0; g_idx[base + 1] = i1; g_idx[base + 2] = i2;
    g_w  [base + 0] = r0 * inv; g_w[base + 1] = r1 * inv; g_w[base + 2] = r2 * inv;
}

// ---------------- kernel 2: interpolation (2 points / thread, tf32-rounded) ----------------
__global__ void interp_kernel(const float* __restrict__ x2) {
    int pair = threadIdx.x >> 6;            // 0..3
    int lane = threadIdx.x & 63;
    int ptA  = blockIdx.x * 8 + pair * 2;
    int ptB  = ptA + 1;
    int b = ptA >> 12;
    int c = lane * 4;

    size_t baseA = (size_t)ptA * 3, baseB = (size_t)ptB * 3;
    int ai0 = g_idx[baseA + 0], ai1 = g_idx[baseA + 1], ai2 = g_idx[baseA + 2];
    int bi0 = g_idx[baseB + 0], bi1 = g_idx[baseB + 1], bi2 = g_idx[baseB + 2];
    float aw0 = g_w[baseA + 0], aw1 = g_w[baseA + 1], aw2 = g_w[baseA + 2];
    float bw0 = g_w[baseB + 0], bw1 = g_w[baseB + 1], bw2 = g_w[baseB + 2];

    const float* xb = x2 + (size_t)b * N2 * C2 + c;
    float4 a0 = *(const float4*)(xb + (size_t)ai0 * C2);
    float4 a1 = *(const float4*)(xb + (size_t)ai1 * C2);
    float4 a2 = *(const float4*)(xb + (size_t)ai2 * C2);
    float4 b0 = *(const float4*)(xb + (size_t)bi0 * C2);
    float4 b1 = *(const float4*)(xb + (size_t)bi1 * C2);
    float4 b2 = *(const float4*)(xb + (size_t)bi2 * C2);

    float4 ra, rb;
    ra.x = tf32r(fmaf(aw0, a0.x, fmaf(aw1, a1.x, aw2 * a2.x)));
    ra.y = tf32r(fmaf(aw0, a0.y, fmaf(aw1, a1.y, aw2 * a2.y)));
    ra.z = tf32r(fmaf(aw0, a0.z, fmaf(aw1, a1.z, aw2 * a2.z)));
    ra.w = tf32r(fmaf(aw0, a0.w, fmaf(aw1, a1.w, aw2 * a2.w)));
    rb.x = tf32r(fmaf(bw0, b0.x, fmaf(bw1, b1.x, bw2 * b2.x)));
    rb.y = tf32r(fmaf(bw0, b0.y, fmaf(bw1, b1.y, bw2 * b2.y)));
    rb.z = tf32r(fmaf(bw0, b0.z, fmaf(bw1, b1.z, bw2 * b2.z)));
    rb.w = tf32r(fmaf(bw0, b0.w, fmaf(bw1, b1.w, bw2 * b2.w)));
    *(float4*)(g_interp + (size_t)ptA * C2 + c) = ra;
    *(float4*)(g_interp + (size_t)ptB * C2 + c) = rb;
}

// ---------------- kernel 3: tf32 mma GEMM, LDSM A-frags + vectorized B-frags ----------------
// grid = b(16) x Mtile(2) x Ntile(2) x splitK(4) = 256 CTAs, 256 threads
// B smem: rows of 128 floats, 16B chunk p stored at p ^ swz(k&3), swz = {0,1,4,5}
// mma #nt covers strided logical cols {nt, nt+8, ..., nt+56} -> thread frags contiguous
__global__ __launch_bounds__(256, 2)
void gemm_mma_kernel() {
    extern __shared__ float sm[];
    const uint32_t smb = smem_u32(sm);

    int bid = blockIdx.x;
    int s   = bid & 3;
    int mtb = (bid >> 2) & 1;
    int ntb = (bid >> 3) & 1;
    int b   = bid >> 4;
    int o0 = mtb * 128, c0 = ntb * 128, k0 = s * KPER;

    int t = threadIdx.x;
    int w = t >> 5, lane = t & 31;
    int g = lane >> 2, kq = lane & 3;
    int warp_m = (w & 3) * 32;
    int warp_n = (w >> 2) * 64;

    const float* Wg = g_Wtf + (size_t)o0 * KTOT + k0;
    const float* Bg = g_interp + ((size_t)b * N1 + k0) * C2 + c0;

    // cp.async slots: W 128x8 float4, B 32x32 float4 (xor-swizzled dst), 4 each per thread
    int wm[4], wq4[4], bk[4], bq4[4];
    uint32_t wdst[4], bdst[4];
#pragma unroll
    for (int i = 0; i < 4; ++i) {
        int li = i * 256 + t;
        wm[i]  = li >> 3;        wq4[i] = (li & 7) * 4;
        int brow = li >> 5, bchunk = li & 31;
        int bsz = (brow & 1) | ((brow & 2) << 1);
        bk[i]  = brow;           bq4[i] = bchunk * 4;
        wdst[i] = (uint32_t)((wm[i] * WS_STRIDE + wq4[i]) * 4);
        bdst[i] = (uint32_t)(WS_BUF * 4 + brow * 512 + (bchunk ^ bsz) * 16);
    }

    // per-thread fragment addresses (bytes within stage)
    uint32_t aoff = (uint32_t)(((warp_m + ((lane >> 3) & 1) * 8 + (lane & 7)) * WS_STRIDE
                                + (lane >> 4) * 4) * 4);
    int swzq = (kq & 1) | ((kq & 2) << 1);
    int cn0  = (w >> 2) * 16;
    uint32_t boffL = (uint32_t)(kq * 512 + ((cn0 + 2 * g) ^ swzq) * 16);
    uint32_t boffH = (uint32_t)(kq * 512 + ((cn0 + 2 * g + 1) ^ swzq) * 16);

    float acc[2][8][4];
#pragma unroll
    for (int mt = 0; mt < 2; ++mt)
#pragma unroll
        for (int nt = 0; nt < 8; ++nt)
#pragma unroll
            for (int r = 0; r < 4; ++r) acc[mt][nt][r] = 0.f;

    // prologue: stages for tiles 0,1
#pragma unroll
    for (int pre = 0; pre < 2; ++pre) {
        uint32_t sb = smb + (uint32_t)(pre * STG_BYTES);
        int kg = pre * KT;
#pragma unroll
        for (int i = 0; i < 4; ++i) {
            cp16(sb + wdst[i], Wg + (size_t)wm[i] * KTOT + kg + wq4[i]);
            cp16(sb + bdst[i], Bg + (size_t)(kg + bk[i]) * C2 + bq4[i]);
        }
        CP_COMMIT();
    }

    int cur = 0;
    int nxt2 = 2 * STG_BYTES;
    for (int kt = 0; kt < NT; ++kt) {
        if (kt == NT - 1) { CP_WAIT(0); } else { CP_WAIT(1); }
        __syncthreads();

        if (kt + 2 < NT) {
            uint32_t sb = smb + (uint32_t)nxt2;
            int kg = (kt + 2) * KT;
#pragma unroll
            for (int i = 0; i < 4; ++i) {
                cp16(sb + wdst[i], Wg + (size_t)wm[i] * KTOT + kg + wq4[i]);
                cp16(sb + bdst[i], Bg + (size_t)(kg + bk[i]) * C2 + bq4[i]);
            }
            CP_COMMIT();
        }

#pragma unroll
        for (int ks = 0; ks < 4; ++ks) {
            int kb = ks * 8;
            uint32_t a0[4], a1[4], bl[8], bh[8];
            uint32_t abase = smb + (uint32_t)cur + (uint32_t)(kb * 4) + aoff;
            ldsm_x4(a0, abase);
            ldsm_x4(a1, abase + 16 * WS_STRIDE * 4);
            uint32_t bbase = smb + (uint32_t)cur + WS_BUF * 4 + (uint32_t)(kb * 512);
            lds128(bl,     bbase + boffL);
            lds128(bl + 4, bbase + boffH);
            lds128(bh,     bbase + boffL + 2048);
            lds128(bh + 4, bbase + boffH + 2048);
#pragma unroll
            for (int nt = 0; nt < 8; ++nt) {
                mma_tf32(acc[0][nt], a0, bl[nt], bh[nt]);
                mma_tf32(acc[1][nt], a1, bl[nt], bh[nt]);
            }
        }

        cur  += STG_BYTES; if (cur  == 3 * STG_BYTES) cur  = 0;
        nxt2 += STG_BYTES; if (nxt2 == 3 * STG_BYTES) nxt2 = 0;
    }

    // epilogue: thread owns 16 consecutive cols per row -> STG.128
    float* out = g_yp[s] + ((size_t)b * OUTCH + o0) * C2 + c0;
    int colb = warp_n + 16 * kq;
#pragma unroll
    for (int mt = 0; mt < 2; ++mt) {
        int r0 = warp_m + mt * 16 + g;
        float* p0 = out + (size_t)r0 * C2 + colb;
        float* p1 = out + (size_t)(r0 + 8) * C2 + colb;
        *(float4*)(p0)      = make_float4(acc[mt][0][0], acc[mt][1][0], acc[mt][2][0], acc[mt][3][0]);
        *(float4*)(p0 + 4)  = make_float4(acc[mt][4][0], acc[mt][5][0], acc[mt][6][0], acc[mt][7][0]);
        *(float4*)(p0 + 8)  = make_float4(acc[mt][0][1], acc[mt][1][1], acc[mt][2][1], acc[mt][3][1]);
        *(float4*)(p0 + 12) = make_float4(acc[mt][4][1], acc[mt][5][1], acc[mt][6][1], acc[mt][7][1]);
        *(float4*)(p1)      = make_float4(acc[mt][0][2], acc[mt][1][2], acc[mt][2][2], acc[mt][3][2]);
        *(float4*)(p1 + 4)  = make_float4(acc[mt][4][2], acc[mt][5][2], acc[mt][6][2], acc[mt][7][2]);
        *(float4*)(p1 + 8)  = make_float4(acc[mt][0][3], acc[mt][1][3], acc[mt][2][3], acc[mt][3][3]);
        *(float4*)(p1 + 12) = make_float4(acc[mt][4][3], acc[mt][5][3], acc[mt][6][3], acc[mt][7][3]);
    }
}

// ---------------- kernel 4: reduce partials + bias + BN stats ----------------
__global__ void reduce_kernel(const float* __restrict__ b1) {
    int c = threadIdx.x;
    int row0 = blockIdx.x * 16;
    float s1 = 0.f, s2 = 0.f;
    for (int r = 0; r < 16; ++r) {
        int row = row0 + r;
        int o = row & (OUTCH - 1);
        size_t idx = (size_t)row * C2 + c;
        float v = b1[o];
#pragma unroll
        for (int s = 0; s < SPLITK; ++s) v += g_yp[s][idx];
        g_y[idx] = v;
        s1 += v;
        s2 = fmaf(v, v, s2);
    }
    atomicAdd(&g_sum[c], s1);
    atomicAdd(&g_sumsq[c], s2);
}

// ---------------- kernel 5: BN + ReLU ----------------
__global__ void bn_kernel(const float* __restrict__ gamma,
                          const float* __restrict__ beta,
                          float* __restrict__ out) {
    int c = threadIdx.x;
    int row = blockIdx.x;
    const float invN = 1.f / (BATCH * OUTCH);
    float mean = g_sum[c] * invN;
    float var  = fmaf(g_sumsq[c], invN, -mean * mean);
    float rstd = rsqrtf(var + BN_EPS);
    float v = g_y[(size_t)row * C2 + c];
    float r = fmaf(gamma[c] * rstd, v - mean, beta[c]);
    out[(size_t)row * C2 + c] = fmaxf(r, 0.f);
}

// ---------------- launcher ----------------
extern "C" void kernel_launch(void* const* d_in, const int* in_sizes, int n_in,
                              void* d_out, int out_size) {
    const float* x2    = (const float*)d_in[1];
    const float* xyz1  = (const float*)d_in[2];
    const float* xyz2  = (const float*)d_in[3];
    const float* W1    = (const float*)d_in[4];
    const float* b1    = (const float*)d_in[5];
    const float* gamma = (const float*)d_in[6];
    const float* beta  = (const float*)d_in[7];
    float* out = (float*)d_out;

    cudaFuncSetAttribute(gemm_mma_kernel,
                         cudaFuncAttributeMaxDynamicSharedMemorySize,
                         SMEM_BYTES);

    convW_kernel<<<(OUTCH * KTOT) / 1024, 256>>>(W1);
    topk_kernel<<<BATCH * 16, 256>>>(xyz1, xyz2);
    interp_kernel<<<(BATCH * N1) / 8, 256>>>(x2);
    gemm_mma_kernel<<<BATCH * 2 * 2 * SPLITK, 256, SMEM_BYTES>>>();
    reduce_kernel<<<(BATCH * OUTCH) / 16, C2>>>(b1);
    bn_kernel<<<BATCH * OUTCH, C2>>>(gamma, beta, out);
}

// round 13
// speedup vs baseline: 1.4623x; 1.3294x over previous
#include <cuda_runtime.h>
#include <cuda_fp16.h>
#include <cstdint>

// ---------------- problem constants ----------------
#define BATCH   16
#define N1      4096
#define N2      1024
#define C2      256
#define OUTCH   256
#define KTOT    4096
#define SPLITK  4
#define KPER    (KTOT/SPLITK)   // 1024
#define KT      64              // K tile
#define NT      (KPER/KT)       // 16 tiles
#define BN_EPS  1e-5f

// smem (bytes): 3 stages of (W 128x72 halves + B 64x136 halves)
#define WROW_H   72              // 144 B row  (4 mod 32 banks -> LDSM conflict-free)
#define BROW_H   136             // 272 B row  (4 mod 32 banks)
#define WS_BYTES (128*WROW_H*2)  // 18432
#define BS_BYTES (64*BROW_H*2)   // 17408
#define STG_BYTES (WS_BYTES + BS_BYTES)   // 35840
#define SMEM_BYTES (3*STG_BYTES)          // 107520

// ---------------- device scratch ----------------
__device__ int    g_idx[BATCH * N1 * 3];
__device__ float  g_w  [BATCH * N1 * 3];
__device__ __half g_Whf[(size_t)OUTCH * KTOT];                 // 2 MB fp16 W
__device__ __half g_interp[(size_t)BATCH * N1 * C2];           // 33.5 MB fp16 A[b][n][c]
__device__ float  g_yp[SPLITK][(size_t)BATCH * OUTCH * C2];    // 16 MB fp32 partials
__device__ float  g_y [(size_t)BATCH * OUTCH * C2];
__device__ float  g_sum[C2];
__device__ float  g_sumsq[C2];

// ---------------- helpers ----------------
__device__ __forceinline__ uint32_t smem_u32(const void* p) {
    uint32_t a;
    asm("{ .reg .u64 t; cvta.to.shared.u64 t, %1; cvt.u32.u64 %0, t; }" : "=r"(a) : "l"(p));
    return a;
}
__device__ __forceinline__ uint32_t h2_bits(__half2 h) {
    uint32_t u;
    memcpy(&u, &h, 4);
    return u;
}
__device__ __forceinline__ void cp16(uint32_t dst, const void* src) {
    asm volatile("cp.async.cg.shared.global [%0], [%1], 16;" :: "r"(dst), "l"(src) : "memory");
}
#define CP_COMMIT()  asm volatile("cp.async.commit_group;" ::: "memory")
#define CP_WAIT(n)   asm volatile("cp.async.wait_group %0;" :: "n"(n) : "memory")

__device__ __forceinline__ void ldsm_x4(uint32_t* r, uint32_t addr) {
    asm volatile("ldmatrix.sync.aligned.m8n8.x4.shared.b16 {%0,%1,%2,%3}, [%4];"
                 : "=r"(r[0]), "=r"(r[1]), "=r"(r[2]), "=r"(r[3]) : "r"(addr));
}
__device__ __forceinline__ void ldsm_x4_t(uint32_t* r, uint32_t addr) {
    asm volatile("ldmatrix.sync.aligned.m8n8.x4.trans.shared.b16 {%0,%1,%2,%3}, [%4];"
                 : "=r"(r[0]), "=r"(r[1]), "=r"(r[2]), "=r"(r[3]) : "r"(addr));
}
__device__ __forceinline__ void mma_f16(float* d, const uint32_t* a, uint32_t b0, uint32_t b1) {
    asm volatile(
        "mma.sync.aligned.m16n8k16.row.col.f32.f16.f16.f32 "
        "{%0,%1,%2,%3}, {%4,%5,%6,%7}, {%8,%9}, {%0,%1,%2,%3};"
        : "+f"(d[0]), "+f"(d[1]), "+f"(d[2]), "+f"(d[3])
        : "r"(a[0]), "r"(a[1]), "r"(a[2]), "r"(a[3]), "r"(b0), "r"(b1));
}

// ---------------- kernel 0: W -> fp16 copy + BN accumulator zeroing ----------------
__global__ void convW_kernel(const float* __restrict__ W1) {
    if (blockIdx.x == 0) {
        g_sum[threadIdx.x] = 0.f;
        g_sumsq[threadIdx.x] = 0.f;
    }
    int i = blockIdx.x * 256 + threadIdx.x;   // float4 index
    float4 v = ((const float4*)W1)[i];
    __half2 h0 = __floats2half2_rn(v.x, v.y);
    __half2 h1 = __floats2half2_rn(v.z, v.w);
    ((uint2*)g_Whf)[i] = make_uint2(h2_bits(h0), h2_bits(h1));
}

// ---------------- kernel 1: 3-NN + weights (dot-product form, packed smem) ----------------
__global__ void topk_kernel(const float* __restrict__ xyz1,
                            const float* __restrict__ xyz2) {
    __shared__ float4 sq[N2];   // (qx, qy, qz, |q|^2)
    int b = blockIdx.x >> 4;
    int nchunk = blockIdx.x & 15;

    const float* p2 = xyz2 + (size_t)b * N2 * 3;
    for (int j = threadIdx.x; j < N2; j += 256) {
        float qx = p2[j * 3 + 0], qy = p2[j * 3 + 1], qz = p2[j * 3 + 2];
        sq[j] = make_float4(qx, qy, qz, fmaf(qx, qx, fmaf(qy, qy, qz * qz)));
    }
    __syncthreads();

    int n = nchunk * 256 + threadIdx.x;
    const float* p1 = xyz1 + ((size_t)b * N1 + n) * 3;
    float px = p1[0], py = p1[1], pz = p1[2];
    float px2 = -2.f * px, py2 = -2.f * py, pz2 = -2.f * pz;
    float pp = fmaf(px, px, fmaf(py, py, pz * pz));

    float d0 = 3.4e38f, d1 = 3.4e38f, d2 = 3.4e38f;
    int   i0 = 0, i1 = 0, i2 = 0;
#pragma unroll 8
    for (int j = 0; j < N2; ++j) {
        float4 q = sq[j];
        float d = fmaf(px2, q.x, fmaf(py2, q.y, fmaf(pz2, q.z, q.w)));
        if (d < d2) {
            if (d < d1) {
                d2 = d1; i2 = i1;
                if (d < d0) { d1 = d0; i1 = i0; d0 = d; i0 = j; }
                else        { d1 = d;  i1 = j; }
            } else { d2 = d; i2 = j; }
        }
    }
    float r0 = 1.f / (d0 + pp + 1e-8f);
    float r1 = 1.f / (d1 + pp + 1e-8f);
    float r2 = 1.f / (d2 + pp + 1e-8f);
    float inv = 1.f / (r0 + r1 + r2);
    size_t base = ((size_t)b * N1 + n) * 3;
    g_idx[base + 0] = i0; g_idx[base + 1] = i1; g_idx[base + 2] = i2;
    g_w  [base + 0] = r0 * inv; g_w[base + 1] = r1 * inv; g_w[base + 2] = r2 * inv;
}

// ---------------- kernel 2: interpolation (2 points / thread) -> fp16 ----------------
__global__ void interp_kernel(const float* __restrict__ x2) {
    int pair = threadIdx.x >> 6;            // 0..3
    int lane = threadIdx.x & 63;
    int ptA  = blockIdx.x * 8 + pair * 2;
    int ptB  = ptA + 1;
    int b = ptA >> 12;
    int c = lane * 4;

    size_t baseA = (size_t)ptA * 3, baseB = (size_t)ptB * 3;
    int ai0 = g_idx[baseA + 0], ai1 = g_idx[baseA + 1], ai2 = g_idx[baseA + 2];
    int bi0 = g_idx[baseB + 0], bi1 = g_idx[baseB + 1], bi2 = g_idx[baseB + 2];
    float aw0 = g_w[baseA + 0], aw1 = g_w[baseA + 1], aw2 = g_w[baseA + 2];
    float bw0 = g_w[baseB + 0], bw1 = g_w[baseB + 1], bw2 = g_w[baseB + 2];

    const float* xb = x2 + (size_t)b * N2 * C2 + c;
    float4 a0 = *(const float4*)(xb + (size_t)ai0 * C2);
    float4 a1 = *(const float4*)(xb + (size_t)ai1 * C2);
    float4 a2 = *(const float4*)(xb + (size_t)ai2 * C2);
    float4 b0 = *(const float4*)(xb + (size_t)bi0 * C2);
    float4 b1 = *(const float4*)(xb + (size_t)bi1 * C2);
    float4 b2 = *(const float4*)(xb + (size_t)bi2 * C2);

    __half2 ha0 = __floats2half2_rn(fmaf(aw0, a0.x, fmaf(aw1, a1.x, aw2 * a2.x)),
                                    fmaf(aw0, a0.y, fmaf(aw1, a1.y, aw2 * a2.y)));
    __half2 ha1 = __floats2half2_rn(fmaf(aw0, a0.z, fmaf(aw1, a1.z, aw2 * a2.z)),
                                    fmaf(aw0, a0.w, fmaf(aw1, a1.w, aw2 * a2.w)));
    __half2 hb0 = __floats2half2_rn(fmaf(bw0, b0.x, fmaf(bw1, b1.x, bw2 * b2.x)),
                                    fmaf(bw0, b0.y, fmaf(bw1, b1.y, bw2 * b2.y)));
    __half2 hb1 = __floats2half2_rn(fmaf(bw0, b0.z, fmaf(bw1, b1.z, bw2 * b2.z)),
                                    fmaf(bw0, b0.w, fmaf(bw1, b1.w, bw2 * b2.w)));
    *(uint2*)(g_interp + (size_t)ptA * C2 + c) = make_uint2(h2_bits(ha0), h2_bits(ha1));
    *(uint2*)(g_interp + (size_t)ptB * C2 + c) = make_uint2(h2_bits(hb0), h2_bits(hb1));
}

// ---------------- kernel 3: fp16 m16n8k16 mma GEMM, 3-stage cp.async ----------------
// grid = b(16) x Mtile(2) x Ntile(2) x splitK(4) = 256 CTAs, 256 threads
__global__ __launch_bounds__(256, 2)
void gemm_mma_kernel() {
    extern __shared__ char smc[];
    const uint32_t smb = smem_u32(smc);

    int bid = blockIdx.x;
    int s   = bid & 3;
    int mtb = (bid >> 2) & 1;
    int ntb = (bid >> 3) & 1;
    int b   = bid >> 4;
    int o0 = mtb * 128, c0 = ntb * 128, k0 = s * KPER;

    int t = threadIdx.x;
    int w = t >> 5, lane = t & 31;
    int g = lane >> 2, kq = lane & 3;
    int warp_m = (w & 3) * 32;
    int warp_n = (w >> 2) * 64;

    const __half* Wg = g_Whf + (size_t)o0 * KTOT + k0;
    const __half* Bg = g_interp + ((size_t)b * N1 + k0) * C2 + c0;

    // cp.async slots: W 128 rows x 8 chunks, B 64 rows x 16 chunks; 4 each / thread
    int wr[4], wc[4], br[4], bc[4];
    uint32_t wdst[4], bdst[4];
#pragma unroll
    for (int i = 0; i < 4; ++i) {
        int li = i * 256 + t;
        wr[i] = li >> 3;  wc[i] = li & 7;
        br[i] = li >> 4;  bc[i] = li & 15;
        wdst[i] = (uint32_t)(wr[i] * (WROW_H * 2) + wc[i] * 16);
        bdst[i] = (uint32_t)(WS_BYTES + br[i] * (BROW_H * 2) + bc[i] * 16);
    }

    // fragment addresses (FIX: warp_n added to B offset)
    int sel = lane >> 3, li8 = lane & 7;
    uint32_t aoff = (uint32_t)(((warp_m + li8 + (sel & 1) * 8) * WROW_H + (sel >> 1) * 8) * 2);
    uint32_t boff = (uint32_t)(WS_BYTES +
                    ((li8 + (sel & 1) * 8) * BROW_H + warp_n + (sel >> 1) * 8) * 2);

    float acc[2][8][4];
#pragma unroll
    for (int mt = 0; mt < 2; ++mt)
#pragma unroll
        for (int nt = 0; nt < 8; ++nt)
#pragma unroll
            for (int r = 0; r < 4; ++r) acc[mt][nt][r] = 0.f;

    // prologue: stages for tiles 0,1
#pragma unroll
    for (int pre = 0; pre < 2; ++pre) {
        uint32_t sb = smb + (uint32_t)(pre * STG_BYTES);
        int kg = pre * KT;
#pragma unroll
        for (int i = 0; i < 4; ++i) {
            cp16(sb + wdst[i], Wg + (size_t)wr[i] * KTOT + kg + wc[i] * 8);
            cp16(sb + bdst[i], Bg + (size_t)(kg + br[i]) * C2 + bc[i] * 8);
        }
        CP_COMMIT();
    }

    int cur = 0;
    int nxt2 = 2 * STG_BYTES;
    for (int kt = 0; kt < NT; ++kt) {
        if (kt == NT - 1) { CP_WAIT(0); } else { CP_WAIT(1); }
        __syncthreads();

        if (kt + 2 < NT) {
            uint32_t sb = smb + (uint32_t)nxt2;
            int kg = (kt + 2) * KT;
#pragma unroll
            for (int i = 0; i < 4; ++i) {
                cp16(sb + wdst[i], Wg + (size_t)wr[i] * KTOT + kg + wc[i] * 8);
                cp16(sb + bdst[i], Bg + (size_t)(kg + br[i]) * C2 + bc[i] * 8);
            }
            CP_COMMIT();
        }

#pragma unroll
        for (int ks = 0; ks < 4; ++ks) {           // 4 x k16 per tile
            uint32_t a0[4], a1[4];
            uint32_t abase = smb + (uint32_t)cur + aoff + (uint32_t)(ks * 32);
            ldsm_x4(a0, abase);
            ldsm_x4(a1, abase + 16 * WROW_H * 2);
            uint32_t bbase = smb + (uint32_t)cur + boff + (uint32_t)(ks * 16 * BROW_H * 2);
#pragma unroll
            for (int p = 0; p < 4; ++p) {          // n-chunk pairs (16 cols each)
                uint32_t r[4];
                ldsm_x4_t(r, bbase + (uint32_t)(p * 32));
                mma_f16(acc[0][2 * p],     a0, r[0], r[1]);
                mma_f16(acc[1][2 * p],     a1, r[0], r[1]);
                mma_f16(acc[0][2 * p + 1], a0, r[2], r[3]);
                mma_f16(acc[1][2 * p + 1], a1, r[2], r[3]);
            }
        }

        cur  += STG_BYTES; if (cur  == 3 * STG_BYTES) cur  = 0;
        nxt2 += STG_BYTES; if (nxt2 == 3 * STG_BYTES) nxt2 = 0;
    }

    // epilogue -> g_yp[s]  (D frag: rows g/g+8, cols nt*8 + 2kq)
    float* out = g_yp[s] + ((size_t)b * OUTCH + o0) * C2 + c0;
#pragma unroll
    for (int mt = 0; mt < 2; ++mt) {
        int r0 = warp_m + mt * 16 + g;
#pragma unroll
        for (int nt = 0; nt < 8; ++nt) {
            int col = warp_n + nt * 8 + kq * 2;
            *(float2*)(out + (size_t)r0 * C2 + col)       = make_float2(acc[mt][nt][0], acc[mt][nt][1]);
            *(float2*)(out + (size_t)(r0 + 8) * C2 + col) = make_float2(acc[mt][nt][2], acc[mt][nt][3]);
        }
    }
}

// ---------------- kernel 4: reduce partials + bias + BN stats ----------------
__global__ void reduce_kernel(const float* __restrict__ b1) {
    int c = threadIdx.x;
    int row0 = blockIdx.x * 16;
    float s1 = 0.f, s2 = 0.f;
    for (int r = 0; r < 16; ++r) {
        int row = row0 + r;
        int o = row & (OUTCH - 1);
        size_t idx = (size_t)row * C2 + c;
        float v = b1[o];
#pragma unroll
        for (int s = 0; s < SPLITK; ++s) v += g_yp[s][idx];
        g_y[idx] = v;
        s1 += v;
        s2 = fmaf(v, v, s2);
    }
    atomicAdd(&g_sum[c], s1);
    atomicAdd(&g_sumsq[c], s2);
}

// ---------------- kernel 5: BN + ReLU ----------------
__global__ void bn_kernel(const float* __restrict__ gamma,
                          const float* __restrict__ beta,
                          float* __restrict__ out) {
    int c = threadIdx.x;
    int row = blockIdx.x;
    const float invN = 1.f / (BATCH * OUTCH);
    float mean = g_sum[c] * invN;
    float var  = fmaf(g_sumsq[c], invN, -mean * mean);
    float rstd = rsqrtf(var + BN_EPS);
    float v = g_y[(size_t)row * C2 + c];
    float r = fmaf(gamma[c] * rstd, v - mean, beta[c]);
    out[(size_t)row * C2 + c] = fmaxf(r, 0.f);
}

// ---------------- launcher ----------------
extern "C" void kernel_launch(void* const* d_in, const int* in_sizes, int n_in,
                              void* d_out, int out_size) {
    const float* x2    = (const float*)d_in[1];
    const float* xyz1  = (const float*)d_in[2];
    const float* xyz2  = (const float*)d_in[3];
    const float* W1    = (const float*)d_in[4];
    const float* b1    = (const float*)d_in[5];
    const float* gamma = (const float*)d_in[6];
    const float* beta  = (const float*)d_in[7];
    float* out = (float*)d_out;

    cudaFuncSetAttribute(gemm_mma_kernel,
                         cudaFuncAttributeMaxDynamicSharedMemorySize,
                         SMEM_BYTES);

    convW_kernel<<<(OUTCH * KTOT) / 1024, 256>>>(W1);
    topk_kernel<<<BATCH * 16, 256>>>(xyz1, xyz2);
    interp_kernel<<<(BATCH * N1) / 8, 256>>>(x2);
    gemm_mma_kernel<<<BATCH * 2 * 2 * SPLITK, 256, SMEM_BYTES>>>();
    reduce_kernel<<<(BATCH * OUTCH) / 16, C2>>>(b1);
    bn_kernel<<<BATCH * OUTCH, C2>>>(gamma, beta, out);
}